// round 6
// baseline (speedup 1.0000x reference)
#include <cuda_runtime.h>
#include <cuda_bf16.h>
#include <cfloat>
#include <cstdint>

#define NUM_HEADS 4
#define OUT_DIM   256
#define HID       512
#define NQ        256
#define TOPK      16
#define N_MEM_MAX 500000
#define CAND      64
#define CPB       8
#define NBLK_MAX  160
#define POOL_MAX  (NBLK_MAX * CPB)        // 1280
#define N_PAD_ROWS (((N_MEM_MAX + 63) / 64) * 64)

// ---------------- static scratch ---------------------------------------------
__device__ __align__(16) float    g_qpre[64 * NUM_HEADS * OUT_DIM];
__device__ __align__(16) float    g_q  [NQ * OUT_DIM];
__device__ __align__(16) uint16_t g_qf8[NQ * (OUT_DIM / 2)];
__device__ __align__(16) uint8_t  g_mem8[(size_t)N_PAD_ROWS * OUT_DIM];  // fp8 copy
__device__ float g_cand_val[NQ * POOL_MAX];
__device__ int   g_cand_idx[NQ * POOL_MAX];

// ---------------- helpers ------------------------------------------------------
__device__ __forceinline__ uint32_t smem_u32(const void* p) {
    return (uint32_t)__cvta_generic_to_shared(p);
}
__device__ __forceinline__ uint16_t cvt_e4m3x2(float hi, float lo) {
    uint16_t r;
    asm("cvt.rn.satfinite.e4m3x2.f32 %0, %1, %2;" : "=h"(r) : "f"(hi), "f"(lo));
    return r;
}
__device__ __forceinline__ void ldsm_x4(uint32_t& r0, uint32_t& r1, uint32_t& r2, uint32_t& r3,
                                        uint32_t addr) {
    asm volatile("ldmatrix.sync.aligned.m8n8.x4.shared.b16 {%0,%1,%2,%3}, [%4];"
                 : "=r"(r0), "=r"(r1), "=r"(r2), "=r"(r3) : "r"(addr));
}
__device__ __forceinline__ void mma_fp8(float* d,
                                        uint32_t a0, uint32_t a1, uint32_t a2, uint32_t a3,
                                        uint32_t b0, uint32_t b1) {
    asm volatile("mma.sync.aligned.m16n8k32.row.col.f32.e4m3.e4m3.f32 "
                 "{%0,%1,%2,%3}, {%4,%5,%6,%7}, {%8,%9}, {%0,%1,%2,%3};"
                 : "+f"(d[0]), "+f"(d[1]), "+f"(d[2]), "+f"(d[3])
                 : "r"(a0), "r"(a1), "r"(a2), "r"(a3), "r"(b0), "r"(b1));
}
__device__ __forceinline__ void cp_async16(uint32_t dst, const void* src) {
    asm volatile("cp.async.cg.shared.global [%0], [%1], 16;"
                 :: "r"(dst), "l"(src) : "memory");
}
#define CP_COMMIT() asm volatile("cp.async.commit_group;" ::: "memory")
#define CP_WAIT2()  asm volatile("cp.async.wait_group 2;" ::: "memory")

__device__ __forceinline__ unsigned long long sort_key(float v, int idx) {
    uint32_t fb = __float_as_uint(v);
    fb ^= (fb & 0x80000000u) ? 0xFFFFFFFFu : 0x80000000u;   // order-preserving flip
    return ((unsigned long long)fb << 32) | (uint32_t)(~idx);
}

// ---------------- K0: mem fp32 -> fp8 (padded with zero rows) ------------------
__global__ __launch_bounds__(256) void cvt_kernel(const float* __restrict__ mem,
                                                  int n_mem, int n_pad_rows) {
    const size_t nchunk = (size_t)n_pad_rows * 16;   // 16 floats per chunk
    for (size_t c = (size_t)blockIdx.x * blockDim.x + threadIdx.x; c < nchunk;
         c += (size_t)gridDim.x * blockDim.x) {
        uint4 o = make_uint4(0u, 0u, 0u, 0u);
        if ((int)(c >> 4) < n_mem) {
            const float4* s = (const float4*)(mem + c * 16);
            const float4 f0 = s[0], f1 = s[1], f2 = s[2], f3 = s[3];
            o.x = (uint32_t)cvt_e4m3x2(f0.y, f0.x) | ((uint32_t)cvt_e4m3x2(f0.w, f0.z) << 16);
            o.y = (uint32_t)cvt_e4m3x2(f1.y, f1.x) | ((uint32_t)cvt_e4m3x2(f1.w, f1.z) << 16);
            o.z = (uint32_t)cvt_e4m3x2(f2.y, f2.x) | ((uint32_t)cvt_e4m3x2(f2.w, f2.z) << 16);
            o.w = (uint32_t)cvt_e4m3x2(f3.y, f3.x) | ((uint32_t)cvt_e4m3x2(f3.w, f3.z) << 16);
        }
        *(uint4*)(g_mem8 + c * 16) = o;
    }
}

// ---------------- K1a: proj = hidden @ Wp + bp --------------------------------
__global__ __launch_bounds__(256) void proj_kernel(const float* __restrict__ hidden,
                                                   const float* __restrict__ Wp,
                                                   const float* __restrict__ bp) {
    const int tid = threadIdx.x;
    const int j   = blockIdx.x * 32 + (tid & 31);
    const int b0  = (tid >> 5) * 8;
    float acc[8];
#pragma unroll
    for (int i = 0; i < 8; i++) acc[i] = 0.f;
#pragma unroll 4
    for (int k = 0; k < HID; k++) {
        const float wv = __ldg(&Wp[k * (NUM_HEADS * OUT_DIM) + j]);
#pragma unroll
        for (int i = 0; i < 8; i++)
            acc[i] = fmaf(__ldg(&hidden[(b0 + i) * HID + k]), wv, acc[i]);
    }
    const float bias = __ldg(&bp[j]);
#pragma unroll
    for (int i = 0; i < 8; i++)
        g_qpre[(b0 + i) * (NUM_HEADS * OUT_DIM) + j] = acc[i] + bias;
}

// ---------------- K1b: layernorm ----------------------------------------------
__global__ __launch_bounds__(256) void ln_kernel() {
    __shared__ float red[OUT_DIM];
    __shared__ float ov[OUT_DIM];
    const int qidx = blockIdx.x;
    const int h = qidx >> 6, b = qidx & 63, d = threadIdx.x;

    const float x = g_qpre[b * (NUM_HEADS * OUT_DIM) + h * OUT_DIM + d];
    red[d] = x; __syncthreads();
    for (int s = 128; s > 0; s >>= 1) { if (d < s) red[d] += red[d + s]; __syncthreads(); }
    const float mean = red[0] * (1.0f / OUT_DIM);
    __syncthreads();
    const float dx = x - mean;
    red[d] = dx * dx; __syncthreads();
    for (int s = 128; s > 0; s >>= 1) { if (d < s) red[d] += red[d + s]; __syncthreads(); }
    const float var = red[0] * (1.0f / OUT_DIM);

    const float o = dx * rsqrtf(var + 1e-5f);
    g_q[qidx * OUT_DIM + d] = o;
    ov[d] = o;
    __syncthreads();
    if (d < 128)
        g_qf8[qidx * 128 + d] = cvt_e4m3x2(ov[2 * d + 1], ov[2 * d]);
}

// ---------------- K2: fp8 scores, 4-stage cp.async ring + fused top-8 ----------
#define B_OFF    0
#define B_STR    272
#define A8_OFF   69632
#define A8_STG   17408          // 64 rows x 272B
#define A8_STR   272
#define SB_OFF   (A8_OFF + 4 * A8_STG)   // 139264
#define SBP      260
#define K2_SMEM  (SB_OFF + 64 * SBP * 2) // 172544

#define INS8(v, r)                                                        \
    do {                                                                  \
        t8v[tminpos] = (v); t8i[tminpos] = (r);                           \
        tmin = t8v[0]; tminpos = 0;                                       \
        _Pragma("unroll")                                                 \
        for (int jj = 1; jj < CPB; jj++)                                  \
            if (t8v[jj] < tmin) { tmin = t8v[jj]; tminpos = jj; }         \
    } while (0)

__global__ __launch_bounds__(256, 1) void score_kernel(int n_mem, int ntiles) {
    extern __shared__ char sm[];
    const int tid = threadIdx.x, lane = tid & 31, w = tid >> 5;
    const int wm = w >> 2, wn = w & 3;
    const uint32_t sb = smem_u32(sm);

    // B fill: 256 q rows x 256B e4m3, row stride 272
    {
        const uint4* src = (const uint4*)g_qf8;
#pragma unroll
        for (int i = 0; i < 16; i++) {
            const int p = tid + i * 256;
            const int q = p >> 4, ch = p & 15;
            *(uint4*)(sm + B_OFF + q * B_STR + ch * 16) = src[q * 16 + ch];
        }
    }

    float t8v[CPB]; int t8i[CPB];
#pragma unroll
    for (int j = 0; j < CPB; j++) { t8v[j] = -FLT_MAX; t8i[j] = 0x7FFFFFFF; }
    float tmin = -FLT_MAX; int tminpos = 0;

    // A loader mapping: thread -> (row = tid>>2, 64B segment = (tid&3)*64)
    const int cr = tid >> 2, cs = (tid & 3) * 64;
    const uint32_t adst0 = sb + A8_OFF + cr * A8_STR + cs;

#define ISSUE_TILE(tl, stg)                                                        \
    do {                                                                           \
        if ((tl) < ntiles) {                                                       \
            const uint8_t* src = g_mem8 + (size_t)((tl) * 64 + cr) * OUT_DIM + cs; \
            const uint32_t d = adst0 + (stg) * A8_STG;                             \
            cp_async16(d + 0, src + 0);  cp_async16(d + 16, src + 16);             \
            cp_async16(d + 32, src + 32); cp_async16(d + 48, src + 48);            \
        }                                                                          \
        CP_COMMIT();                                                               \
    } while (0)

    // prologue: 3 tiles in flight
    ISSUE_TILE(blockIdx.x + 0 * gridDim.x, 0);
    ISSUE_TILE(blockIdx.x + 1 * gridDim.x, 1);
    ISSUE_TILE(blockIdx.x + 2 * gridDim.x, 2);

    const uint32_t bB = sb + B_OFF + (wn * 64 + (lane & 15)) * B_STR + (lane >> 4) * 16;
    __nv_bfloat16* Sb = (__nv_bfloat16*)(sm + SB_OFF);

    int it = 0;
    for (int t = blockIdx.x; t < ntiles; t += gridDim.x, it++) {
        const int stg = it & 3;
        CP_WAIT2();
        __syncthreads();                 // stage `stg` visible to all

        ISSUE_TILE(t + 3 * gridDim.x, (it + 3) & 3);

        const uint32_t aB = sb + A8_OFF + stg * A8_STG
                          + (wm * 32 + (lane & 15)) * A8_STR + (lane >> 4) * 16;

        float acc[2][8][4];
#pragma unroll
        for (int mt = 0; mt < 2; mt++)
#pragma unroll
            for (int nt = 0; nt < 8; nt++)
#pragma unroll
                for (int c = 0; c < 4; c++) acc[mt][nt][c] = 0.f;

#pragma unroll
        for (int kt = 0; kt < 8; kt++) {
            uint32_t a0, a1, a2, a3, a4, a5, a6, a7;
            ldsm_x4(a0, a1, a2, a3, aB + kt * 32);
            ldsm_x4(a4, a5, a6, a7, aB + 16 * A8_STR + kt * 32);
#pragma unroll
            for (int qg = 0; qg < 4; qg++) {
                uint32_t b0, b1, b2, b3;
                ldsm_x4(b0, b1, b2, b3, bB + qg * 16 * B_STR + kt * 32);
                mma_fp8(acc[0][qg * 2 + 0], a0, a1, a2, a3, b0, b2);
                mma_fp8(acc[0][qg * 2 + 1], a0, a1, a2, a3, b1, b3);
                mma_fp8(acc[1][qg * 2 + 0], a4, a5, a6, a7, b0, b2);
                mma_fp8(acc[1][qg * 2 + 1], a4, a5, a6, a7, b1, b3);
            }
        }

        // scores -> Sb [64 r][256 q] bf16
#pragma unroll
        for (int mt = 0; mt < 2; mt++) {
            const int rl = wm * 32 + mt * 16 + (lane >> 2);
#pragma unroll
            for (int nt = 0; nt < 8; nt++) {
                const int q = wn * 64 + nt * 8 + (lane & 3) * 2;
                *(__nv_bfloat162*)(Sb + rl * SBP + q) =
                    __float22bfloat162_rn(make_float2(acc[mt][nt][0], acc[mt][nt][1]));
                *(__nv_bfloat162*)(Sb + (rl + 8) * SBP + q) =
                    __float22bfloat162_rn(make_float2(acc[mt][nt][2], acc[mt][nt][3]));
            }
        }
        __syncthreads();                 // Sb ready; mma done (stage reuse safe)

        // fused selection: thread tid owns query tid
        const int rb = t * 64;
        const int rcap = n_mem - rb;
#pragma unroll 4
        for (int r = 0; r < 64; r++) {
            const float v = __bfloat162float(Sb[r * SBP + tid]);
            if (v > tmin && r < rcap) INS8(v, rb + r);
        }
    }

    const int ob = (tid * gridDim.x + blockIdx.x) * CPB;
#pragma unroll
    for (int j = 0; j < CPB; j++) { g_cand_val[ob + j] = t8v[j]; g_cand_idx[ob + j] = t8i[j]; }
#undef ISSUE_TILE
}

// ---------------- K3: rank-select top-64 -> exact rescore -> top-16 ------------
__global__ __launch_bounds__(256) void final_kernel(const float* __restrict__ mem,
                                                    float* __restrict__ out,
                                                    int n_mem, int nblk) {
    __shared__ unsigned long long keys[POOL_MAX];
    __shared__ int   si[POOL_MAX];
    __shared__ int   ci[CAND];
    __shared__ float ev[CAND];
    __shared__ unsigned long long k2[CAND];
    __shared__ float wv[TOPK]; __shared__ int wi[TOPK];

    const int q = blockIdx.x, tid = threadIdx.x, lane = tid & 31, w = tid >> 5;
    const int P = nblk * CPB;

    for (int j = tid; j < P; j += 256) {
        const float v = g_cand_val[q * P + j];
        const int  id = g_cand_idx[q * P + j];
        keys[j] = sort_key(v, id);
        si[j] = id;
    }
    if (tid < CAND) { ci[tid] = 0x7FFFFFFF; ev[tid] = -FLT_MAX; }
    __syncthreads();

    // rank-count: thread owns candidates tid, tid+256, ...
    unsigned long long mk[5]; int mrank[5]; int mc[5]; int cnt = 0;
    for (int c = tid; c < P; c += 256) { mk[cnt] = keys[c]; mc[cnt] = c; mrank[cnt] = 0; cnt++; }
    for (int j = 0; j < P; j++) {
        const unsigned long long kj = keys[j];   // broadcast read
#pragma unroll 5
        for (int i = 0; i < cnt; i++)
            if (kj > mk[i]) mrank[i]++;
    }
    for (int i = 0; i < cnt; i++)
        if (mrank[i] < CAND) ci[mrank[i]] = si[mc[i]];
    __syncthreads();

    // exact fp32 rescore of 64 candidates
    const float* qv = g_q + q * OUT_DIM;
    for (int c = w; c < CAND; c += 8) {
        const int id = ci[c];
        float sum = 0.f;
        if (id < n_mem) {
            const float* row = mem + (size_t)id * OUT_DIM;
#pragma unroll
            for (int d = lane; d < OUT_DIM; d += 32) sum += row[d] * qv[d];
        }
#pragma unroll
        for (int o = 16; o; o >>= 1) sum += __shfl_xor_sync(0xffffffffu, sum, o);
        if (lane == 0) ev[c] = (id < n_mem) ? sum : -FLT_MAX;
    }
    __syncthreads();

    if (tid < CAND) k2[tid] = sort_key(ev[tid], ci[tid]);
    __syncthreads();
    if (tid < CAND) {
        const unsigned long long mine = k2[tid];
        int r = 0;
#pragma unroll
        for (int j = 0; j < CAND; j++)
            if (k2[j] > mine) r++;
        if (r < TOPK) { wv[r] = ev[tid]; wi[r] = ci[tid]; }
    }
    __syncthreads();

    float* out_scores = out;
    float* out_idx    = out + NQ * TOPK;
    float* out_feats  = out + 2 * NQ * TOPK;

    if (tid < TOPK) {
        out_scores[q * TOPK + tid] = wv[tid];
        out_idx[q * TOPK + tid]    = (float)wi[tid];
    }
#pragma unroll 1
    for (int kk = 0; kk < TOPK; kk++)
        out_feats[(size_t)(q * TOPK + kk) * OUT_DIM + tid] = mem[(size_t)wi[kk] * OUT_DIM + tid];
}

// ---------------- launch ------------------------------------------------------
extern "C" void kernel_launch(void* const* d_in, const int* in_sizes, int n_in,
                              void* d_out, int out_size) {
    const float* hidden = (const float*)d_in[0];
    const float* Wp     = (const float*)d_in[1];
    const float* bp     = (const float*)d_in[2];
    const float* mem    = (const float*)d_in[3];
    int n_mem = in_sizes[3] / OUT_DIM;
    if (n_mem > N_MEM_MAX) n_mem = N_MEM_MAX;
    const int ntiles = (n_mem + 63) / 64;
    const int n_pad_rows = ntiles * 64;

    int dev = 0;
    cudaGetDevice(&dev);
    int nsm = 148;
    cudaDeviceGetAttribute(&nsm, cudaDevAttrMultiProcessorCount, dev);
    if (nsm < 1) nsm = 148;
    if (nsm > NBLK_MAX) nsm = NBLK_MAX;
    if (nsm > ntiles) nsm = ntiles;

    cudaFuncSetAttribute(score_kernel, cudaFuncAttributeMaxDynamicSharedMemorySize, K2_SMEM);

    cvt_kernel<<<2048, 256>>>(mem, n_mem, n_pad_rows);
    proj_kernel<<<(NUM_HEADS * OUT_DIM) / 32, 256>>>(hidden, Wp, bp);
    ln_kernel<<<NQ, 256>>>();
    score_kernel<<<nsm, 256, K2_SMEM>>>(n_mem, ntiles);
    final_kernel<<<NQ, 256>>>(mem, (float*)d_out, n_mem, nsm);
}

// round 7
// speedup vs baseline: 2.4813x; 2.4813x over previous
#include <cuda_runtime.h>
#include <cuda_bf16.h>
#include <cfloat>
#include <cstdint>

#define NUM_HEADS 4
#define OUT_DIM   256
#define HID       512
#define NQ        256
#define TOPK      16
#define N_MEM_MAX 500000
#define CAND      32
#define CPB       4                       // candidates per (query, half, block)
#define NBLK_MAX  152
#define POOL_MAX  (2 * NBLK_MAX * CPB)    // 1216 per query
#define PMAX_PAD  1280

// ---------------- static scratch ---------------------------------------------
__device__ __align__(16) float          g_qpre[64 * NUM_HEADS * OUT_DIM];
__device__ __align__(16) float          g_q [NQ * OUT_DIM];
__device__ __align__(16) __nv_bfloat16  g_qb[NQ * OUT_DIM];
__device__ float g_cand_val[NQ * POOL_MAX];
__device__ int   g_cand_idx[NQ * POOL_MAX];

// ---------------- helpers ------------------------------------------------------
__device__ __forceinline__ uint32_t smem_u32(const void* p) {
    return (uint32_t)__cvta_generic_to_shared(p);
}
// pack high halves of two fp32 -> bf16x2 (truncation; pure ALU)
__device__ __forceinline__ uint32_t bf16x2_trunc(float lo, float hi) {
    uint32_t r;
    asm("prmt.b32 %0, %1, %2, 0x7632;" : "=r"(r) : "r"(__float_as_uint(lo)), "r"(__float_as_uint(hi)));
    return r;
}
__device__ __forceinline__ void ldsm_x4(uint32_t& r0, uint32_t& r1, uint32_t& r2, uint32_t& r3,
                                        uint32_t addr) {
    asm volatile("ldmatrix.sync.aligned.m8n8.x4.shared.b16 {%0,%1,%2,%3}, [%4];"
                 : "=r"(r0), "=r"(r1), "=r"(r2), "=r"(r3) : "r"(addr));
}
__device__ __forceinline__ void mma_bf16(float* d,
                                         uint32_t a0, uint32_t a1, uint32_t a2, uint32_t a3,
                                         uint32_t b0, uint32_t b1) {
    asm volatile("mma.sync.aligned.m16n8k16.row.col.f32.bf16.bf16.f32 "
                 "{%0,%1,%2,%3}, {%4,%5,%6,%7}, {%8,%9}, {%0,%1,%2,%3};"
                 : "+f"(d[0]), "+f"(d[1]), "+f"(d[2]), "+f"(d[3])
                 : "r"(a0), "r"(a1), "r"(a2), "r"(a3), "r"(b0), "r"(b1));
}
__device__ __forceinline__ unsigned long long sort_key(float v, int idx) {
    uint32_t fb = __float_as_uint(v);
    fb ^= (fb & 0x80000000u) ? 0xFFFFFFFFu : 0x80000000u;
    return ((unsigned long long)fb << 32) | (uint32_t)(~idx);
}

// ---------------- K1a: proj = hidden @ Wp + bp (128 blocks) -------------------
__global__ __launch_bounds__(256) void proj_kernel(const float* __restrict__ hidden,
                                                   const float* __restrict__ Wp,
                                                   const float* __restrict__ bp) {
    const int tid = threadIdx.x;
    const int jb = blockIdx.x & 31, bh = blockIdx.x >> 5;       // 32 col-blocks x 4 batch-quarters
    const int j  = jb * 32 + (tid & 31);
    const int b0 = bh * 16 + (tid >> 5) * 2;
    float acc0 = 0.f, acc1 = 0.f;
#pragma unroll 4
    for (int k = 0; k < HID; k++) {
        const float wv = __ldg(&Wp[k * (NUM_HEADS * OUT_DIM) + j]);
        acc0 = fmaf(__ldg(&hidden[(b0 + 0) * HID + k]), wv, acc0);
        acc1 = fmaf(__ldg(&hidden[(b0 + 1) * HID + k]), wv, acc1);
    }
    const float bias = __ldg(&bp[j]);
    g_qpre[(b0 + 0) * (NUM_HEADS * OUT_DIM) + j] = acc0 + bias;
    g_qpre[(b0 + 1) * (NUM_HEADS * OUT_DIM) + j] = acc1 + bias;
}

// ---------------- K1b: layernorm ----------------------------------------------
__global__ __launch_bounds__(256) void ln_kernel() {
    __shared__ float red[OUT_DIM];
    const int qidx = blockIdx.x;
    const int h = qidx >> 6, b = qidx & 63, d = threadIdx.x;

    const float x = g_qpre[b * (NUM_HEADS * OUT_DIM) + h * OUT_DIM + d];
    red[d] = x; __syncthreads();
    for (int s = 128; s > 0; s >>= 1) { if (d < s) red[d] += red[d + s]; __syncthreads(); }
    const float mean = red[0] * (1.0f / OUT_DIM);
    __syncthreads();
    const float dx = x - mean;
    red[d] = dx * dx; __syncthreads();
    for (int s = 128; s > 0; s >>= 1) { if (d < s) red[d] += red[d + s]; __syncthreads(); }
    const float var = red[0] * (1.0f / OUT_DIM);

    const float o = dx * rsqrtf(var + 1e-5f);
    g_q [qidx * OUT_DIM + d] = o;
    g_qb[qidx * OUT_DIM + d] = __float2bfloat16(o);
}

// ---------------- K2: bf16 mma, 512 thr, 32-row tiles, fused top-4x2 ----------
#define K2_THREADS 512
#define TROWS 32
#define LDB   264                        // bf16 elems per B row (528B)
#define B_BYTES (NQ * LDB * 2)           // 135168
#define A_BYTES (TROWS * LDB * 2)        // 16896
#define SBP   260
#define SB_BYTES (TROWS * SBP * 2)       // 16640
#define K2_SMEM (B_BYTES + 2 * A_BYTES + SB_BYTES)   // 185600

#define INS4(v, r)                                                        \
    do {                                                                  \
        t4v[tminpos] = (v); t4i[tminpos] = (r);                           \
        tmin = t4v[0]; tminpos = 0;                                       \
        _Pragma("unroll")                                                 \
        for (int jj = 1; jj < CPB; jj++)                                  \
            if (t4v[jj] < tmin) { tmin = t4v[jj]; tminpos = jj; }         \
    } while (0)

__global__ __launch_bounds__(K2_THREADS, 1) void score_kernel(const float* __restrict__ mem,
                                                              int n_mem, int ntiles) {
    extern __shared__ char sm[];
    char* Bs  = sm;                       // queries bf16 [256][LDB]
    char* A0  = sm + B_BYTES;             // 2 x [32 rows][LDB]
    __nv_bfloat16* Sb = (__nv_bfloat16*)(sm + B_BYTES + 2 * A_BYTES);
    const uint32_t sb = smem_u32(sm);

    const int tid = threadIdx.x, lane = tid & 31, w = tid >> 5;   // 16 warps
    // B fill: 256 queries x 512B
    {
        const uint4* src = (const uint4*)g_qb;
#pragma unroll
        for (int i = 0; i < 8; i++) {
            const int p = tid + i * K2_THREADS;
            const int q = p >> 3, ch = p & 7;          // 8 chunks of 16B per 512B row
            uint4 v = src[q * 32 + ch * 4 / 4 * 4];    // placeholder; fixed below
        }
    }
    // (real B fill, 4 bf16 per uint2 like R3)
    {
        const uint2* src = (const uint2*)g_qb;
        for (int p = tid; p < NQ * 64; p += K2_THREADS) {
            const int q = p >> 6, c4 = p & 63;
            *(uint2*)(Bs + q * (LDB * 2) + c4 * 8) = src[p];
        }
    }

    // selection state: thread covers query (tid&255), row half (tid>>8)
    const int myq = tid & 255, half = tid >> 8;
    float t4v[CPB]; int t4i[CPB];
#pragma unroll
    for (int j = 0; j < CPB; j++) { t4v[j] = -FLT_MAX; t4i[j] = 0x7FFFFFFF; }
    float tmin = -FLT_MAX; int tminpos = 0;

    // A loader: thread -> row tid>>4 (0..31), col group (tid&15)*16 floats
    const int ar = tid >> 4, ac = (tid & 15) * 16;
    const uint32_t asts0 = sb + B_BYTES + ar * (LDB * 2) + ac * 2;

    float4 f[4];
#define LDG_T(tl)                                                                   \
    do {                                                                            \
        const int rg = (tl) * TROWS + ar;                                           \
        if (rg < n_mem) {                                                           \
            const float4* s = (const float4*)(mem + (size_t)rg * OUT_DIM + ac);     \
            f[0] = s[0]; f[1] = s[1]; f[2] = s[2]; f[3] = s[3];                     \
        } else {                                                                    \
            f[0] = f[1] = f[2] = f[3] = make_float4(0.f, 0.f, 0.f, 0.f);            \
        }                                                                           \
    } while (0)

#define STS_T(bufi)                                                                 \
    do {                                                                            \
        const uint32_t d = asts0 + (bufi) * A_BYTES;                                \
        uint4 o0, o1;                                                               \
        o0.x = bf16x2_trunc(f[0].x, f[0].y); o0.y = bf16x2_trunc(f[0].z, f[0].w);   \
        o0.z = bf16x2_trunc(f[1].x, f[1].y); o0.w = bf16x2_trunc(f[1].z, f[1].w);   \
        o1.x = bf16x2_trunc(f[2].x, f[2].y); o1.y = bf16x2_trunc(f[2].z, f[2].w);   \
        o1.z = bf16x2_trunc(f[3].x, f[3].y); o1.w = bf16x2_trunc(f[3].z, f[3].w);   \
        asm volatile("st.shared.v4.b32 [%0], {%1,%2,%3,%4};" ::                     \
            "r"(d), "r"(o0.x), "r"(o0.y), "r"(o0.z), "r"(o0.w) : "memory");         \
        asm volatile("st.shared.v4.b32 [%0], {%1,%2,%3,%4};" ::                     \
            "r"(d + 16), "r"(o1.x), "r"(o1.y), "r"(o1.z), "r"(o1.w) : "memory");    \
    } while (0)

    // prologue
    LDG_T(blockIdx.x);
    STS_T(0);
    __syncthreads();

    // warp tile: 32 rows x 16 queries (wn = w)
    const uint32_t bB = sb + (w * 16 + (lane & 15)) * (LDB * 2) + (lane >> 4) * 16;

    int it = 0;
    for (int t = blockIdx.x; t < ntiles; t += gridDim.x, it++) {
        const int cur = it & 1;
        const int tn = t + gridDim.x;
        if (tn < ntiles) LDG_T(tn);       // hide LDG under mma

        const uint32_t aB = sb + B_BYTES + cur * A_BYTES
                          + (lane & 15) * (LDB * 2) + (lane >> 4) * 16;

        float acc[2][2][4];
#pragma unroll
        for (int mt = 0; mt < 2; mt++)
#pragma unroll
            for (int nt = 0; nt < 2; nt++)
#pragma unroll
                for (int c = 0; c < 4; c++) acc[mt][nt][c] = 0.f;

#pragma unroll
        for (int kt = 0; kt < 16; kt++) {
            uint32_t a0, a1, a2, a3, a4, a5, a6, a7;
            ldsm_x4(a0, a1, a2, a3, aB + kt * 32);
            ldsm_x4(a4, a5, a6, a7, aB + 16 * (LDB * 2) + kt * 32);
            uint32_t b0, b1, b2, b3;
            ldsm_x4(b0, b1, b2, b3, bB + kt * 32);
            mma_bf16(acc[0][0], a0, a1, a2, a3, b0, b2);
            mma_bf16(acc[0][1], a0, a1, a2, a3, b1, b3);
            mma_bf16(acc[1][0], a4, a5, a6, a7, b0, b2);
            mma_bf16(acc[1][1], a4, a5, a6, a7, b1, b3);
        }

        // scores -> Sb [32 r][256 q]
#pragma unroll
        for (int mt = 0; mt < 2; mt++) {
            const int rl = mt * 16 + (lane >> 2);
#pragma unroll
            for (int nt = 0; nt < 2; nt++) {
                const int q = w * 16 + nt * 8 + (lane & 3) * 2;
                *(__nv_bfloat162*)(Sb + rl * SBP + q) =
                    __float22bfloat162_rn(make_float2(acc[mt][nt][0], acc[mt][nt][1]));
                *(__nv_bfloat162*)(Sb + (rl + 8) * SBP + q) =
                    __float22bfloat162_rn(make_float2(acc[mt][nt][2], acc[mt][nt][3]));
            }
        }
        __syncthreads();                  // Sb complete; mma[cur] done everywhere

        // fused selection: 2 threads per query, 16 rows each
        {
            const int rb = t * TROWS + half * 16;
            const int rcap = n_mem - rb;
#pragma unroll 4
            for (int r = 0; r < 16; r++) {
                const float v = __bfloat162float(Sb[(half * 16 + r) * SBP + myq]);
                if (v > tmin && r < rcap) INS4(v, rb + r);
            }
        }

        // stage t+1 into other buffer
        if (tn < ntiles) STS_T(cur ^ 1);
        __syncthreads();                  // A[cur^1] ready; Sb free
    }

    const int ob = ((myq * 2 + half) * gridDim.x + blockIdx.x) * CPB;
#pragma unroll
    for (int j = 0; j < CPB; j++) { g_cand_val[ob + j] = t4v[j]; g_cand_idx[ob + j] = t4i[j]; }
#undef LDG_T
#undef STS_T
}

// ---------------- K3: rank-select top-32 -> exact rescore -> top-16 ------------
__global__ __launch_bounds__(256) void final_kernel(const float* __restrict__ mem,
                                                    float* __restrict__ out,
                                                    int n_mem, int P) {
    __shared__ unsigned long long keys[PMAX_PAD];
    __shared__ int   si[PMAX_PAD];
    __shared__ int   ci[CAND];
    __shared__ float ev[CAND];
    __shared__ unsigned long long k2[CAND];
    __shared__ float wv[TOPK]; __shared__ int wi[TOPK];

    const int q = blockIdx.x, tid = threadIdx.x, lane = tid & 31, w = tid >> 5;

    for (int j = tid; j < PMAX_PAD; j += 256) {
        if (j < P) {
            const float v = g_cand_val[q * P + j];
            const int  id = g_cand_idx[q * P + j];
            keys[j] = sort_key(v, id);
            si[j] = id;
        } else { keys[j] = 0ull; si[j] = 0x7FFFFFFF; }
    }
    if (tid < CAND) { ci[tid] = 0x7FFFFFFF; }
    __syncthreads();

    // rank-count: thread owns exactly 5 candidates (tid + i*256)
    unsigned long long mk[5]; int mrank[5];
#pragma unroll
    for (int i = 0; i < 5; i++) { mk[i] = keys[tid + i * 256]; mrank[i] = 0; }
    for (int j = 0; j < PMAX_PAD; j++) {
        const unsigned long long kj = keys[j];
#pragma unroll
        for (int i = 0; i < 5; i++)
            if (kj > mk[i]) mrank[i]++;
    }
#pragma unroll
    for (int i = 0; i < 5; i++)
        if (mrank[i] < CAND && mk[i] != 0ull) ci[mrank[i]] = si[tid + i * 256];
    __syncthreads();

    // exact fp32 rescore
    const float* qv = g_q + q * OUT_DIM;
    for (int c = w; c < CAND; c += 8) {
        const int id = ci[c];
        float sum = 0.f;
        if (id < n_mem) {
            const float* row = mem + (size_t)id * OUT_DIM;
#pragma unroll
            for (int d = lane; d < OUT_DIM; d += 32) sum += row[d] * qv[d];
        }
#pragma unroll
        for (int o = 16; o; o >>= 1) sum += __shfl_xor_sync(0xffffffffu, sum, o);
        if (lane == 0) ev[c] = (id < n_mem) ? sum : -FLT_MAX;
    }
    __syncthreads();

    if (tid < CAND) k2[tid] = sort_key(ev[tid], ci[tid]);
    __syncthreads();
    if (tid < CAND) {
        const unsigned long long mine = k2[tid];
        int r = 0;
#pragma unroll
        for (int j = 0; j < CAND; j++)
            if (k2[j] > mine) r++;
        if (r < TOPK) { wv[r] = ev[tid]; wi[r] = ci[tid]; }
    }
    __syncthreads();

    float* out_scores = out;
    float* out_idx    = out + NQ * TOPK;
    float* out_feats  = out + 2 * NQ * TOPK;

    if (tid < TOPK) {
        out_scores[q * TOPK + tid] = wv[tid];
        out_idx[q * TOPK + tid]    = (float)wi[tid];
    }
#pragma unroll 1
    for (int kk = 0; kk < TOPK; kk++)
        out_feats[(size_t)(q * TOPK + kk) * OUT_DIM + tid] = mem[(size_t)wi[kk] * OUT_DIM + tid];
}

// ---------------- launch ------------------------------------------------------
extern "C" void kernel_launch(void* const* d_in, const int* in_sizes, int n_in,
                              void* d_out, int out_size) {
    const float* hidden = (const float*)d_in[0];
    const float* Wp     = (const float*)d_in[1];
    const float* bp     = (const float*)d_in[2];
    const float* mem    = (const float*)d_in[3];
    int n_mem = in_sizes[3] / OUT_DIM;
    if (n_mem > N_MEM_MAX) n_mem = N_MEM_MAX;
    const int ntiles = (n_mem + TROWS - 1) / TROWS;

    int dev = 0;
    cudaGetDevice(&dev);
    int nsm = 148;
    cudaDeviceGetAttribute(&nsm, cudaDevAttrMultiProcessorCount, dev);
    if (nsm < 1) nsm = 148;
    if (nsm > NBLK_MAX) nsm = NBLK_MAX;
    if (nsm > ntiles) nsm = ntiles;

    cudaFuncSetAttribute(score_kernel, cudaFuncAttributeMaxDynamicSharedMemorySize, K2_SMEM);

    proj_kernel<<<128, 256>>>(hidden, Wp, bp);
    ln_kernel<<<NQ, 256>>>();
    score_kernel<<<nsm, 512, K2_SMEM>>>(mem, n_mem, ntiles);
    final_kernel<<<NQ, 256>>>(mem, (float*)d_out, n_mem, 2 * nsm * CPB);
}